// round 12
// baseline (speedup 1.0000x reference)
#include <cuda_runtime.h>
#include <cuda_bf16.h>
#include <cstdint>
#include <math.h>

#define B_   64
#define C_   192
#define C2_  384
#define HW_  3136            // 56*56
#define M_   (B_*HW_)        // 200704
#define PST  58              // padded row stride for plane smem buffers

typedef unsigned long long ull;

// ---------------- scratch (device globals), all channel-major ---------------
__device__ float g_y0    [M_*C_];    // dwconv out  [C][B*HW]
__device__ float g_t1    [M_*C2_];   // lin1 out    [2C][B*HW]  (x | z planes)
__device__ float g_xc    [M_*C_];    // dct1 result [C][B*HW]
__device__ float g_otT   [M_*C_];    // outline transposed [C][B*HW]
__device__ float g_xd    [M_*C2_];   // dct2 result [2C][B*HW]
__device__ float g_yg    [M_*C_];    // LN*silu     [C][B*HW]
__device__ float g_femixT [HW_*C_];  // [C][HW]
__device__ float g_mult1T [HW_*C_];
__device__ float g_otmeanT[HW_*C_];
__device__ float g_xmeanT [HW_*C2_];
__device__ float g_skftT  [HW_*C2_];
__device__ float g_mult2T [HW_*C2_];
__device__ float g_cos  [HW_];       // cos[n][h]
__device__ float g_cosT [HW_];       // cos[h][n]
__device__ float g_cosP [HW_];       // doubly-permuted (mode-1 B operand)
__device__ float g_dval [HW_];       // wn^2+wm^2 at spatial p=n*56+m

// --------------------------- packed f32x2 helpers ---------------------------
__device__ __forceinline__ ull dup2(float v){
    ull r; asm("mov.b64 %0, {%1, %1};" : "=l"(r) : "f"(v)); return r;
}
__device__ __forceinline__ void fma2(ull &c, ull a, ull b){
    asm("fma.rn.f32x2 %0, %1, %2, %3;" : "=l"(c) : "l"(a), "l"(b), "l"(c));
}
__device__ __forceinline__ ull mul2(ull a, ull b){
    ull r; asm("mul.rn.f32x2 %0, %1, %2;" : "=l"(r) : "l"(a), "l"(b)); return r;
}

// ------------------------------- init --------------------------------------
__device__ __forceinline__ float cosv(int n, int h){
    const float PI = 3.14159265358979323846f;
    float v = cosf((float)n * ((h + 0.5f)/56.0f) * PI) * sqrtf(2.0f/56.0f);
    if (n == 0) v *= 0.70710678118654752440f;
    return v;
}
__global__ void init_k(){
    int i = blockIdx.x*blockDim.x + threadIdx.x;
    if (i >= HW_) return;
    int a = i/56, b = i%56;
    g_cos [i] = cosv(a, b);
    g_cosT[i] = cosv(b, a);
    int ja = (a%28)*2 + a/28;
    int jb = (b%28)*2 + b/28;
    g_cosP[i] = cosv(jb, ja);
    const float PI = 3.14159265358979323846f;
    float wn = PI*(float)a/56.0f, wm = PI*(float)b/56.0f;
    g_dval[i] = wn*wn + wm*wm;
}

// -------------------- depthwise 3x3 conv, plane -> plane -------------------
__global__ __launch_bounds__(256) void dwconv_k(const float* __restrict__ x,
        const float* __restrict__ wc, const float* __restrict__ bc){
    __shared__ float sp[58][58];
    int id = blockIdx.x;
    int c = id % C_, b = id / C_;
    const float* xp = x + ((size_t)b*C_ + c)*HW_;
    int t = threadIdx.x;
    for (int i = t; i < 58*58; i += 256) sp[i/58][i%58] = 0.f;
    __syncthreads();
    for (int i = t; i < HW_; i += 256) sp[i/56 + 1][i%56 + 1] = xp[i];
    float w[9];
    #pragma unroll
    for (int k = 0; k < 9; k++) w[k] = wc[c*9 + k];
    float bias = bc[c];
    __syncthreads();
    float* yp = g_y0 + (size_t)c*M_ + (size_t)b*HW_;
    for (int i = t; i < HW_; i += 256){
        int r = i/56, q = i%56;
        float a = bias;
        #pragma unroll
        for (int dy = 0; dy < 3; dy++)
            #pragma unroll
            for (int dx = 0; dx < 3; dx++)
                a += sp[r+dy][q+dx]*w[dy*3+dx];
        yp[i] = a;
    }
}

// ------------------- transpose outline NHWC -> otT cm ----------------------
__global__ __launch_bounds__(256) void transp_k(const float* __restrict__ in){
    __shared__ float tile[32][33];
    int c0 = blockIdx.x*32;
    int r0 = blockIdx.y*32;
    int lane = threadIdx.x & 31, w = threadIdx.x >> 5;
    #pragma unroll
    for (int i = w; i < 32; i += 8)
        tile[i][lane] = in[(size_t)(r0+i)*C_ + c0 + lane];
    __syncthreads();
    #pragma unroll
    for (int i = w; i < 32; i += 8)
        g_otT[(size_t)(c0+i)*M_ + r0 + lane] = tile[lane][i];
}

// ---------- otmeanT = mean_b(otT); femixT = otmeanT + freq_embed^T ---------
__global__ void otfemix_k(const float* __restrict__ fe){
    int i4 = blockIdx.x*blockDim.x + threadIdx.x;
    if (i4 >= HW_*C_/4) return;
    int c = i4 / (HW_/4), p4 = i4 - c*(HW_/4);
    const float* base = g_otT + (size_t)c*M_ + p4*4;
    float4 s = make_float4(0,0,0,0);
    #pragma unroll 8
    for (int b = 0; b < B_; b++){
        float4 v = *(const float4*)(base + (size_t)b*HW_);
        s.x += v.x; s.y += v.y; s.z += v.z; s.w += v.w;
    }
    const float inv = 1.0f/B_;
    float4 m = make_float4(s.x*inv, s.y*inv, s.z*inv, s.w*inv);
    ((float4*)g_otmeanT)[i4] = m;
    int p = p4*4;
    float4 f = make_float4(fe[(size_t)(p+0)*C_ + c], fe[(size_t)(p+1)*C_ + c],
                           fe[(size_t)(p+2)*C_ + c], fe[(size_t)(p+3)*C_ + c]);
    ((float4*)g_femixT)[i4] = make_float4(m.x+f.x, m.y+f.y, m.z+f.z, m.w+f.w);
}

// ----- xmeanT[c2][p]: c2<C from mean_b(xc); c2>=C copy otmeanT --------------
__global__ void xmean_k(){
    int i4 = blockIdx.x*blockDim.x + threadIdx.x;
    if (i4 >= HW_*C2_/4) return;
    int c2 = i4 / (HW_/4), p4 = i4 - c2*(HW_/4);
    if (c2 < C_){
        const float* base = g_xc + (size_t)c2*M_ + p4*4;
        float4 s = make_float4(0,0,0,0);
        #pragma unroll 8
        for (int b = 0; b < B_; b++){
            float4 v = *(const float4*)(base + (size_t)b*HW_);
            s.x += v.x; s.y += v.y; s.z += v.z; s.w += v.w;
        }
        const float inv = 1.0f/B_;
        ((float4*)g_xmeanT)[i4] = make_float4(s.x*inv, s.y*inv, s.z*inv, s.w*inv);
    } else {
        ((float4*)g_xmeanT)[i4] = ((const float4*)g_otmeanT)[(size_t)(c2-C_)*(HW_/4) + p4];
    }
}

// ---------------- SIMT NN GEMM on channel-major small tensors --------------
template<int EPI>
__global__ __launch_bounds__(256) void cmgemm_k(
        const float* __restrict__ W, const float* __restrict__ X,
        const float* __restrict__ bias, float* __restrict__ Cout,
        int M, int N, int K)
{
    __shared__ float As[16][68];
    __shared__ float Bs[16][68];
    int t = threadIdx.x;
    int m0 = blockIdx.y*64, n0 = blockIdx.x*64;
    int ty = t >> 4, tx = t & 15;
    float acc[4][4];
    #pragma unroll
    for (int i = 0; i < 4; i++){ acc[i][0]=0;acc[i][1]=0;acc[i][2]=0;acc[i][3]=0; }

    int am = t >> 2, akk = (t & 3)*4;
    int bk = t >> 4, bf = (t & 15)*4;

    for (int k0 = 0; k0 < K; k0 += 16){
        float4 wa = *(const float4*)&W[(size_t)(m0+am)*K + k0 + akk];
        float4 xb = *(const float4*)&X[(size_t)(k0+bk)*N + n0 + bf];
        __syncthreads();
        As[akk+0][am] = wa.x; As[akk+1][am] = wa.y;
        As[akk+2][am] = wa.z; As[akk+3][am] = wa.w;
        *(float4*)&Bs[bk][bf] = xb;
        __syncthreads();
        #pragma unroll
        for (int k = 0; k < 16; k++){
            float a[4], b[4];
            #pragma unroll
            for (int i = 0; i < 4; i++) a[i] = As[k][ty*4+i];
            #pragma unroll
            for (int j = 0; j < 4; j++) b[j] = Bs[k][tx*4+j];
            #pragma unroll
            for (int i = 0; i < 4; i++)
                #pragma unroll
                for (int j = 0; j < 4; j++) acc[i][j] += a[i]*b[j];
        }
    }
    #pragma unroll
    for (int i = 0; i < 4; i++){
        int m = m0 + ty*4 + i;
        float bm = bias[m];
        float4 v;
        float* vp = &v.x;
        #pragma unroll
        for (int j = 0; j < 4; j++){
            float u = acc[i][j] + bm;
            if (EPI == 1){
                u = fmaxf(u, 0.f);
                u = expf(-u * g_dval[n0 + tx*4 + j]);
            }
            vp[j] = u;
        }
        *(float4*)&Cout[(size_t)m*N + n0 + tx*4] = v;
    }
}

// ------------------------ tf32 tensor-core NN GEMM -------------------------
// Fragment-packed smem (LDS.64 fragment gathers).  EPI 0: cm store.
// EPI 1: NCHW scatter.  EPI 3: LayerNorm over 192 cols + *silu(Z) -> cm store
// (requires gridDim.x == 1 so each block owns all 192 channels of its rows).
__device__ __forceinline__ float to_tf32(float x){
    uint32_t u; asm("cvt.rna.tf32.f32 %0, %1;" : "=r"(u) : "f"(x));
    return __uint_as_float(u);
}
__device__ __forceinline__ void mma_tf32(float c[4], const uint32_t a[4], const uint32_t b[2]){
    asm volatile("mma.sync.aligned.m16n8k8.row.col.f32.tf32.tf32.f32 "
        "{%0,%1,%2,%3}, {%4,%5,%6,%7}, {%8,%9}, {%0,%1,%2,%3};"
        : "+f"(c[0]), "+f"(c[1]), "+f"(c[2]), "+f"(c[3])
        : "r"(a[0]), "r"(a[1]), "r"(a[2]), "r"(a[3]), "r"(b[0]), "r"(b[1]));
}

template<int EPI>
__global__ __launch_bounds__(256) void tgemm_k(
        const float* __restrict__ X, const float* __restrict__ Wm,
        const float* __restrict__ bias, float* __restrict__ Cout,
        int K,
        const float* __restrict__ gam = nullptr,
        const float* __restrict__ bet = nullptr,
        const float* __restrict__ Z = nullptr)
{
    __shared__ float As2[2][16*136];     // 16 k-rows x 68 f2 (=136 floats)
    __shared__ float Bs2[2][2*1584];     // 2 ks8-planes x 792 f2 (=1584 floats)
    __shared__ float redS[2][128], redQ[2][128];
    const int t = threadIdx.x;
    const int lane = t & 31, warp = t >> 5;
    const int gid = lane >> 2, tig = lane & 3;
    const int wm = warp & 3, wn = warp >> 2;
    const int m0 = wm*32, n0 = wn*96;
    const int row0 = blockIdx.y*128, col0 = blockIdx.x*192;

    float acc[2][12][4];
    #pragma unroll
    for (int mt = 0; mt < 2; mt++)
        #pragma unroll
        for (int nt = 0; nt < 12; nt++)
            #pragma unroll
            for (int q = 0; q < 4; q++) acc[mt][nt][q] = 0.f;

    // ---- A global + store mapping ----
    const int af4 = t & 31, ak = t >> 5;
    const float* Ag = X + (size_t)ak*M_ + row0 + af4*4;
    const int sbb = af4 >> 2;
    const int scomp = (af4 >> 1) & 1;
    int smf[4];
    #pragma unroll
    for (int i = 0; i < 4; i++){
        int g = 4*(af4 & 1) + i;
        smf[i] = (8*sbb + (g ^ sbb))*2 + scomp;
    }

    // ---- B global + store mapping ----
    int brow[3], bbase[3];
    const float* Bg[3];
    #pragma unroll
    for (int r = 0; r < 3; r++){
        int idx = t + r*256;
        brow[r] = idx >> 2;
        int bk = (idx & 3)*4;
        Bg[r] = Wm + (size_t)(col0 + brow[r])*K + bk;
        bbase[r] = ((bk >> 3)*792 + brow[r])*2 + ((bk >> 2) & 1);
    }

    // ---- read-side fragment offsets ----
    int amf[2];
    #pragma unroll
    for (int mt = 0; mt < 2; mt++){
        int b = wm*2 + mt;
        amf[mt] = 8*b + (gid ^ b);
    }
    const int bb = tig*196 + n0 + gid;

    float4 pa0, pa1, pb[3];
    pa0 = *(const float4*)(Ag);
    pa1 = *(const float4*)(Ag + (size_t)8*M_);
    #pragma unroll
    for (int r = 0; r < 3; r++) pb[r] = *(const float4*)(Bg[r]);

    auto stash = [&](int s){
        float* A = As2[s]; float* Bb = Bs2[s];
        const float* p0 = &pa0.x; const float* p1 = &pa1.x;
        #pragma unroll
        for (int i = 0; i < 4; i++){
            A[ak*136 + smf[i]]     = to_tf32(p0[i]);
            A[(ak+8)*136 + smf[i]] = to_tf32(p1[i]);
        }
        #pragma unroll
        for (int r = 0; r < 3; r++){
            const float* pB = &pb[r].x;
            #pragma unroll
            for (int i = 0; i < 4; i++)
                Bb[bbase[r] + i*392] = to_tf32(pB[i]);
        }
    };

    stash(0);
    __syncthreads();

    const int nIter = K >> 4;
    int s = 0;
    for (int it = 0; it < nIter; it++){
        if (it + 1 < nIter){
            int k0 = (it+1) << 4;
            pa0 = *(const float4*)(Ag + (size_t)k0*M_);
            pa1 = *(const float4*)(Ag + (size_t)(k0+8)*M_);
            #pragma unroll
            for (int r = 0; r < 3; r++) pb[r] = *(const float4*)(Bg[r] + k0);
        }
        const float2* Ap = (const float2*)As2[s];
        const float2* Bp = (const float2*)Bs2[s];
        #pragma unroll
        for (int ks = 0; ks < 16; ks += 8){
            uint32_t af[2][4];
            #pragma unroll
            for (int mt = 0; mt < 2; mt++){
                float2 lo = Ap[(ks+tig)*68 + amf[mt]];
                float2 hi = Ap[(ks+tig+4)*68 + amf[mt]];
                af[mt][0] = __float_as_uint(lo.x);
                af[mt][1] = __float_as_uint(lo.y);
                af[mt][2] = __float_as_uint(hi.x);
                af[mt][3] = __float_as_uint(hi.y);
            }
            uint32_t bf[12][2];
            int bo = (ks >> 3)*792 + bb;
            #pragma unroll
            for (int nt = 0; nt < 12; nt++){
                float2 bv = Bp[bo + nt*8];
                bf[nt][0] = __float_as_uint(bv.x);
                bf[nt][1] = __float_as_uint(bv.y);
            }
            #pragma unroll
            for (int mt = 0; mt < 2; mt++)
                #pragma unroll
                for (int nt = 0; nt < 12; nt++)
                    mma_tf32(acc[mt][nt], af[mt], bf[nt]);
        }
        if (it + 1 < nIter){
            int sn = s ^ 1;
            stash(sn);
            __syncthreads();
            s = sn;
        }
    }

    if (EPI == 3){
        // bias, then LayerNorm across all 192 cols of each row, then *silu(Z)
        #pragma unroll
        for (int mt = 0; mt < 2; mt++)
            #pragma unroll
            for (int nt = 0; nt < 12; nt++){
                int cc = col0 + n0 + nt*8 + tig*2;
                float b0v = bias[cc], b1v = bias[cc+1];
                acc[mt][nt][0] += b0v; acc[mt][nt][1] += b1v;
                acc[mt][nt][2] += b0v; acc[mt][nt][3] += b1v;
            }
        float sA[2], qA[2], sB[2], qB[2];
        #pragma unroll
        for (int mt = 0; mt < 2; mt++){
            sA[mt]=0.f; qA[mt]=0.f; sB[mt]=0.f; qB[mt]=0.f;
            #pragma unroll
            for (int nt = 0; nt < 12; nt++){
                float v0=acc[mt][nt][0], v1=acc[mt][nt][1];
                float v2=acc[mt][nt][2], v3=acc[mt][nt][3];
                sA[mt]+=v0+v1; qA[mt]+=v0*v0+v1*v1;
                sB[mt]+=v2+v3; qB[mt]+=v2*v2+v3*v3;
            }
            #pragma unroll
            for (int o = 1; o <= 2; o <<= 1){
                sA[mt]+=__shfl_xor_sync(0xffffffffu,sA[mt],o);
                qA[mt]+=__shfl_xor_sync(0xffffffffu,qA[mt],o);
                sB[mt]+=__shfl_xor_sync(0xffffffffu,sB[mt],o);
                qB[mt]+=__shfl_xor_sync(0xffffffffu,qB[mt],o);
            }
        }
        __syncthreads();
        if (tig == 0){
            #pragma unroll
            for (int mt = 0; mt < 2; mt++){
                int rl = m0 + mt*16 + gid;
                redS[wn][rl]   = sA[mt]; redQ[wn][rl]   = qA[mt];
                redS[wn][rl+8] = sB[mt]; redQ[wn][rl+8] = qB[mt];
            }
        }
        __syncthreads();
        const float invC = 1.0f/C_;
        #pragma unroll
        for (int mt = 0; mt < 2; mt++){
            int rl0 = m0 + mt*16 + gid, rl1 = rl0 + 8;
            int r0 = row0 + rl0, r1 = row0 + rl1;
            float mu0 = (redS[0][rl0]+redS[1][rl0])*invC;
            float mu1 = (redS[0][rl1]+redS[1][rl1])*invC;
            float va0 = fmaxf((redQ[0][rl0]+redQ[1][rl0])*invC - mu0*mu0, 0.f);
            float va1 = fmaxf((redQ[0][rl1]+redQ[1][rl1])*invC - mu1*mu1, 0.f);
            float rs0 = rsqrtf(va0 + 1e-5f), rs1 = rsqrtf(va1 + 1e-5f);
            #pragma unroll
            for (int nt = 0; nt < 12; nt++){
                int cc = col0 + n0 + nt*8 + tig*2;
                float g0 = gam[cc], g1 = gam[cc+1];
                float e0 = bet[cc], e1 = bet[cc+1];
                float z00 = Z[(size_t)cc*M_ + r0], z01 = Z[(size_t)(cc+1)*M_ + r0];
                float z10 = Z[(size_t)cc*M_ + r1], z11 = Z[(size_t)(cc+1)*M_ + r1];
                float o00 = ((acc[mt][nt][0]-mu0)*rs0*g0 + e0) * (z00/(1.f+expf(-z00)));
                float o01 = ((acc[mt][nt][1]-mu0)*rs0*g1 + e1) * (z01/(1.f+expf(-z01)));
                float o10 = ((acc[mt][nt][2]-mu1)*rs1*g0 + e0) * (z10/(1.f+expf(-z10)));
                float o11 = ((acc[mt][nt][3]-mu1)*rs1*g1 + e1) * (z11/(1.f+expf(-z11)));
                Cout[(size_t)cc    *M_ + r0] = o00;
                Cout[(size_t)(cc+1)*M_ + r0] = o01;
                Cout[(size_t)cc    *M_ + r1] = o10;
                Cout[(size_t)(cc+1)*M_ + r1] = o11;
            }
        }
        return;
    }

    #pragma unroll
    for (int mt = 0; mt < 2; mt++){
        #pragma unroll
        for (int nt = 0; nt < 12; nt++){
            int r0 = row0 + m0 + mt*16 + gid;
            int cc = col0 + n0 + nt*8 + tig*2;
            float b0v = bias[cc], b1v = bias[cc+1];
            float v00 = acc[mt][nt][0] + b0v, v01 = acc[mt][nt][1] + b1v;
            float v10 = acc[mt][nt][2] + b0v, v11 = acc[mt][nt][3] + b1v;
            if (EPI == 0){
                Cout[(size_t)cc    *M_ + r0    ] = v00;
                Cout[(size_t)(cc+1)*M_ + r0    ] = v01;
                Cout[(size_t)cc    *M_ + r0 + 8] = v10;
                Cout[(size_t)(cc+1)*M_ + r0 + 8] = v11;
            } else {   // EPI 1: NCHW scatter
                int b0i = r0 / HW_,     p0i = r0 - b0i*HW_;
                int b1i = (r0+8) / HW_, p1i = (r0+8) - b1i*HW_;
                Cout[((size_t)(b0i*C_ + cc  ))*HW_ + p0i] = v00;
                Cout[((size_t)(b0i*C_ + cc+1))*HW_ + p0i] = v01;
                Cout[((size_t)(b1i*C_ + cc  ))*HW_ + p1i] = v10;
                Cout[((size_t)(b1i*C_ + cc+1))*HW_ + p1i] = v11;
            }
        }
    }
}

// ---------------- fused DCT2D * mult * IDCT2D per 56x56 plane --------------
// Folded transforms (mirror symmetry): every matmul has K=28.
// 2 warps per plane (even/odd output rows), 2 planes per block (128 threads).
template<int MODE>
__global__ __launch_bounds__(128) void dct_k(const float* __restrict__ inA,
                                             const float* __restrict__ inB,
                                             float* __restrict__ outA,
                                             const float* __restrict__ multT,
                                             const float* __restrict__ cosB)
{
    extern __shared__ float sh[];
    float* CsH = sh;                     // [56][28] stride 29
    float* CbF = sh + 56*29;             // [28][56] stride 58
    const int tid  = threadIdx.x;
    const int wid  = tid >> 5, lane = tid & 31;
    const int pl   = wid >> 1;
    const int p    = wid & 1;
    float* P0 = sh + 56*29 + 28*58 + pl*(2*56*PST);
    float* P1 = P0 + 56*PST;

    for (int idx = tid; idx < 56*28; idx += 128){
        int n = idx/28, k = idx - n*28;
        CsH[n*29 + k] = g_cos[n*56 + k];
    }
    for (int idx = tid; idx < 28*56; idx += 128){
        int k = idx/56, m = idx - k*56;
        CbF[k*58 + m] = cosB[k*56 + m];
    }

    const int id = blockIdx.x*2 + pl;
    int b, s = 0, c;
    if (MODE == 0){ b = id / C_; c = id - b*C_; }
    else { b = id / C2_; int rr = id - b*C2_; s = rr / C_; c = rr - s*C_; }
    const float* pinA = inA + (size_t)c*M_ + (size_t)b*HW_;
    const float* pinB = (MODE==1) ? inB + (size_t)c*M_ + (size_t)b*HW_ : nullptr;

    {
        int tl = tid & 63;
        for (int f = tl; f < 1568; f += 64){
            int r = f/28, q = f - r*28;
            if (MODE == 0){
                *(ull*)&P0[r*PST + 2*q] = *(const ull*)(pinA + r*56 + 2*q);
            } else {
                int par = q/14, u = (q - par*14)*2;
                const float* src = par ? pinB : pinA;
                *(ull*)&P0[r*PST + par*28 + u] = *(const ull*)(src + r*56 + 28*s + u);
            }
        }
    }
    __syncthreads();

    const bool act = (lane < 28);
    const int ri = lane >> 2;
    const int tc = (lane & 3)*14;
    const int coff = (MODE==1 && tc >= 28) ? 28 : 0;
    ull acc[4][7];
    ull bvec[7];

    auto rowfold = [&](){
        for (int idx = lane; idx < 1568; idx += 32){
            int hh = idx/56, w = idx - hh*56;
            float a = P0[hh*PST + w], bb = P0[(55-hh)*PST + w];
            P1[(28*p + hh)*PST + w] = p ? (a - bb) : (a + bb);
        }
    };
    auto colfold = [&](){
        for (int idx = lane; idx < 784; idx += 32){
            int nn = idx/28, wt = idx - nn*28;
            int n = 2*nn + p;
            float a = P0[n*PST + wt], bb = P0[n*PST + 55 - wt];
            if (MODE == 0){
                P1[(28*p + nn)*PST + 2*wt]     = a + bb;
                P1[(28*p + nn)*PST + 2*wt + 1] = a - bb;
            } else {
                P1[(28*p + nn)*PST + wt]      = a + bb;
                P1[(28*p + nn)*PST + 28 + wt] = a - bb;
            }
        }
    };
    auto mmRow = [&](){
        #pragma unroll
        for (int i = 0; i < 4; i++)
            #pragma unroll
            for (int j = 0; j < 7; j++) acc[i][j] = 0ULL;
        #pragma unroll 4
        for (int k = 0; k < 28; k++){
            const float* brow = &P1[(28*p + k)*PST + tc];
            #pragma unroll
            for (int j = 0; j < 7; j++) bvec[j] = *(const ull*)(brow + 2*j);
            #pragma unroll
            for (int i = 0; i < 4; i++){
                int n = 2*(ri*4 + i) + p;
                ull ad = dup2(CsH[n*29 + k]);
                #pragma unroll
                for (int j = 0; j < 7; j++) fma2(acc[i][j], ad, bvec[j]);
            }
        }
    };
    auto mmCol = [&](){
        #pragma unroll
        for (int i = 0; i < 4; i++)
            #pragma unroll
            for (int j = 0; j < 7; j++) acc[i][j] = 0ULL;
        #pragma unroll 4
        for (int k = 0; k < 28; k++){
            const float* brow = &CbF[k*58 + tc];
            #pragma unroll
            for (int j = 0; j < 7; j++) bvec[j] = *(const ull*)(brow + 2*j);
            #pragma unroll
            for (int i = 0; i < 4; i++){
                int sr = 28*p + ri*4 + i;
                ull ad;
                if (MODE == 0) ad = *(const ull*)&P1[sr*PST + 2*k];
                else           ad = dup2(P1[sr*PST + k + coff]);
                #pragma unroll
                for (int j = 0; j < 7; j++) fma2(acc[i][j], ad, bvec[j]);
            }
        }
    };

    rowfold();
    __syncthreads();
    if (act){
        mmRow();
        #pragma unroll
        for (int i = 0; i < 4; i++){
            int n = 2*(ri*4 + i) + p;
            #pragma unroll
            for (int j = 0; j < 7; j++) *(ull*)&P0[n*PST + tc + 2*j] = acc[i][j];
        }
    }
    __syncwarp();
    colfold();
    __syncwarp();
    if (act){
        mmCol();
        int par = (MODE==1) ? tc/28 : 0;
        const float* mp = multT + (size_t)(c + C_*par)*HW_;
        int mc = (MODE==1) ? (28*s + (tc - par*28)) : tc;
        #pragma unroll
        for (int i = 0; i < 4; i++){
            int n = 2*(ri*4 + i) + p;
            #pragma unroll
            for (int j = 0; j < 7; j++){
                ull mv = *(const ull*)&mp[n*56 + mc + 2*j];
                *(ull*)&P0[n*PST + tc + 2*j] = mul2(acc[i][j], mv);
            }
        }
    }
    __syncthreads();
    rowfold();
    __syncthreads();
    if (act){
        mmRow();
        #pragma unroll
        for (int i = 0; i < 4; i++){
            int n = 2*(ri*4 + i) + p;
            #pragma unroll
            for (int j = 0; j < 7; j++) *(ull*)&P0[n*PST + tc + 2*j] = acc[i][j];
        }
    }
    __syncwarp();
    colfold();
    __syncwarp();
    if (act){
        mmCol();
        int par = (MODE==1) ? tc/28 : 0;
        float* op = outA + (size_t)(c + C_*par)*M_ + (size_t)b*HW_;
        int oc = (MODE==1) ? (28*s + (tc - par*28)) : tc;
        #pragma unroll
        for (int i = 0; i < 4; i++){
            int n = 2*(ri*4 + i) + p;
            #pragma unroll
            for (int j = 0; j < 7; j++)
                *(ull*)&op[n*56 + oc + 2*j] = acc[i][j];
        }
    }
}

// --------------------------------- launch ----------------------------------
extern "C" void kernel_launch(void* const* d_in, const int* in_sizes, int n_in,
                              void* d_out, int out_size)
{
    const float* x        = (const float*)d_in[0];
    const float* fe       = (const float*)d_in[1];
    const float* ot       = (const float*)d_in[2];
    const float* dw_w     = (const float*)d_in[3];
    const float* dw_b     = (const float*)d_in[4];
    const float* lin_w    = (const float*)d_in[5];
    const float* lin_b    = (const float*)d_in[6];
    const float* tok_w    = (const float*)d_in[7];
    const float* tok_b    = (const float*)d_in[8];
    const float* lin2_w   = (const float*)d_in[9];
    const float* lin2_b   = (const float*)d_in[10];
    const float* tok2_w   = (const float*)d_in[11];
    const float* tok2_b   = (const float*)d_in[12];
    const float* lin3_w   = (const float*)d_in[13];
    const float* lin3_b   = (const float*)d_in[14];
    const float* norm_g   = (const float*)d_in[15];
    const float* norm_b   = (const float*)d_in[16];
    const float* out_w    = (const float*)d_in[17];
    const float* out_b    = (const float*)d_in[18];
    float* out = (float*)d_out;

    float *y0, *t1, *xc, *otT, *xd, *yg;
    float *femixT, *mult1T, *xmeanT, *skftT, *mult2T;
    float *cosT, *cosP;
    cudaGetSymbolAddress((void**)&y0,     g_y0);
    cudaGetSymbolAddress((void**)&t1,     g_t1);
    cudaGetSymbolAddress((void**)&xc,     g_xc);
    cudaGetSymbolAddress((void**)&otT,    g_otT);
    cudaGetSymbolAddress((void**)&xd,     g_xd);
    cudaGetSymbolAddress((void**)&yg,     g_yg);
    cudaGetSymbolAddress((void**)&femixT, g_femixT);
    cudaGetSymbolAddress((void**)&mult1T, g_mult1T);
    cudaGetSymbolAddress((void**)&xmeanT, g_xmeanT);
    cudaGetSymbolAddress((void**)&skftT,  g_skftT);
    cudaGetSymbolAddress((void**)&mult2T, g_mult2T);
    cudaGetSymbolAddress((void**)&cosT,   g_cosT);
    cudaGetSymbolAddress((void**)&cosP,   g_cosP);

    const int DCT_SMEM = (56*29 + 28*58 + 2*2*56*PST) * 4;   // 64960 B
    cudaFuncSetAttribute(dct_k<0>, cudaFuncAttributeMaxDynamicSharedMemorySize, DCT_SMEM);
    cudaFuncSetAttribute(dct_k<1>, cudaFuncAttributeMaxDynamicSharedMemorySize, DCT_SMEM);

    init_k<<<(HW_+255)/256, 256>>>();
    dwconv_k<<<B_*C_, 256>>>(x, dw_w, dw_b);
    transp_k<<<dim3(C_/32, M_/32), 256>>>(ot);
    otfemix_k<<<(HW_*C_/4 + 255)/256, 256>>>(fe);

    // mult1T = exp(-relu(tok_w @ femixT + b) * dval)
    cmgemm_k<1><<<dim3(HW_/64, C_/64), 256>>>(tok_w, femixT, tok_b, mult1T,
                                              C_, HW_, C_);
    // t1 = lin_w @ y0  (tf32 TC, fragment-packed)
    tgemm_k<0><<<dim3(2, M_/128), 256>>>(y0, lin_w, lin_b, t1, C_);
    // xc = dct-filter-idct (mode 0)
    dct_k<0><<<B_*C_/2, 128, DCT_SMEM>>>(t1, nullptr, xc, mult1T, cosT);

    xmean_k<<<(HW_*C2_/4 + 255)/256, 256>>>();
    // skftT = lin2 @ xmeanT + b
    cmgemm_k<0><<<dim3(HW_/64, C2_/64), 256>>>(lin2_w, xmeanT, lin2_b, skftT,
                                               C2_, HW_, C2_);
    // mult2T = exp(-relu(tok2 @ skftT + b) * dval)
    cmgemm_k<1><<<dim3(HW_/64, C2_/64), 256>>>(tok2_w, skftT, tok2_b, mult2T,
                                               C2_, HW_, C2_);
    // xd = interleaved dct-filter-idct (mode 1)
    dct_k<1><<<B_*C2_/2, 128, DCT_SMEM>>>(xc, otT, xd, mult2T, cosP);

    // yg = LN(lin3 @ xd + b) * silu(z)   [fused epilogue, grid.x == 1]
    tgemm_k<3><<<dim3(1, M_/128), 256>>>(xd, lin3_w, lin3_b, yg, C2_,
                                         norm_g, norm_b, t1 + (size_t)C_*M_);
    // out = out_w @ yg, NCHW
    tgemm_k<1><<<dim3(1, M_/128), 256>>>(yg, out_w, out_b, out, C_);
}

// round 13
// speedup vs baseline: 1.0125x; 1.0125x over previous
#include <cuda_runtime.h>
#include <cuda_bf16.h>
#include <cstdint>
#include <math.h>

#define B_   64
#define C_   192
#define C2_  384
#define HW_  3136            // 56*56
#define M_   (B_*HW_)        // 200704
#define PST  58              // padded row stride for plane smem buffers

typedef unsigned long long ull;

// ---------------- scratch (device globals), all channel-major ---------------
__device__ float g_y0    [M_*C_];    // dwconv out  [C][B*HW]
__device__ float g_t1    [M_*C2_];   // lin1 out    [2C][B*HW]  (x | z planes)
__device__ float g_xc    [M_*C_];    // dct1 result [C][B*HW]
__device__ float g_otT   [M_*C_];    // outline transposed [C][B*HW]
__device__ float g_xd    [M_*C2_];   // dct2 result [2C][B*HW]
__device__ float g_yg    [M_*C_];    // LN*silu     [C][B*HW]
__device__ float g_femixT [HW_*C_];  // [C][HW]
__device__ float g_mult1T [HW_*C_];
__device__ float g_otmeanT[HW_*C_];
__device__ float g_xmeanT [HW_*C2_];
__device__ float g_skftT  [HW_*C2_];
__device__ float g_mult2T [HW_*C2_];
__device__ float g_cos  [HW_];       // cos[n][h]
__device__ float g_cosT [HW_];       // cos[h][n]
__device__ float g_cosP [HW_];       // doubly-permuted (mode-1 B operand)
__device__ float g_dval [HW_];       // wn^2+wm^2 at spatial p=n*56+m

// --------------------------- packed f32x2 helpers ---------------------------
__device__ __forceinline__ ull dup2(float v){
    ull r; asm("mov.b64 %0, {%1, %1};" : "=l"(r) : "f"(v)); return r;
}
__device__ __forceinline__ void fma2(ull &c, ull a, ull b){
    asm("fma.rn.f32x2 %0, %1, %2, %3;" : "=l"(c) : "l"(a), "l"(b), "l"(c));
}
__device__ __forceinline__ ull mul2(ull a, ull b){
    ull r; asm("mul.rn.f32x2 %0, %1, %2;" : "=l"(r) : "l"(a), "l"(b)); return r;
}

// ------------------------------- init --------------------------------------
__device__ __forceinline__ float cosv(int n, int h){
    const float PI = 3.14159265358979323846f;
    float v = cosf((float)n * ((h + 0.5f)/56.0f) * PI) * sqrtf(2.0f/56.0f);
    if (n == 0) v *= 0.70710678118654752440f;
    return v;
}
__global__ void init_k(){
    int i = blockIdx.x*blockDim.x + threadIdx.x;
    if (i >= HW_) return;
    int a = i/56, b = i%56;
    g_cos [i] = cosv(a, b);
    g_cosT[i] = cosv(b, a);
    int ja = (a%28)*2 + a/28;
    int jb = (b%28)*2 + b/28;
    g_cosP[i] = cosv(jb, ja);
    const float PI = 3.14159265358979323846f;
    float wn = PI*(float)a/56.0f, wm = PI*(float)b/56.0f;
    g_dval[i] = wn*wn + wm*wm;
}

// -------------------- depthwise 3x3 conv, plane -> plane -------------------
__global__ __launch_bounds__(256) void dwconv_k(const float* __restrict__ x,
        const float* __restrict__ wc, const float* __restrict__ bc){
    __shared__ float sp[58][58];
    int id = blockIdx.x;
    int c = id % C_, b = id / C_;
    const float* xp = x + ((size_t)b*C_ + c)*HW_;
    int t = threadIdx.x;
    for (int i = t; i < 58*58; i += 256) sp[i/58][i%58] = 0.f;
    __syncthreads();
    for (int i = t; i < HW_; i += 256) sp[i/56 + 1][i%56 + 1] = xp[i];
    float w[9];
    #pragma unroll
    for (int k = 0; k < 9; k++) w[k] = wc[c*9 + k];
    float bias = bc[c];
    __syncthreads();
    float* yp = g_y0 + (size_t)c*M_ + (size_t)b*HW_;
    for (int i = t; i < HW_; i += 256){
        int r = i/56, q = i%56;
        float a = bias;
        #pragma unroll
        for (int dy = 0; dy < 3; dy++)
            #pragma unroll
            for (int dx = 0; dx < 3; dx++)
                a += sp[r+dy][q+dx]*w[dy*3+dx];
        yp[i] = a;
    }
}

// ------------------- transpose outline NHWC -> otT cm ----------------------
__global__ __launch_bounds__(256) void transp_k(const float* __restrict__ in){
    __shared__ float tile[32][33];
    int c0 = blockIdx.x*32;
    int r0 = blockIdx.y*32;
    int lane = threadIdx.x & 31, w = threadIdx.x >> 5;
    #pragma unroll
    for (int i = w; i < 32; i += 8)
        tile[i][lane] = in[(size_t)(r0+i)*C_ + c0 + lane];
    __syncthreads();
    #pragma unroll
    for (int i = w; i < 32; i += 8)
        g_otT[(size_t)(c0+i)*M_ + r0 + lane] = tile[lane][i];
}

// ---------- otmeanT = mean_b(otT); femixT = otmeanT + freq_embed^T ---------
__global__ void otfemix_k(const float* __restrict__ fe){
    int i4 = blockIdx.x*blockDim.x + threadIdx.x;
    if (i4 >= HW_*C_/4) return;
    int c = i4 / (HW_/4), p4 = i4 - c*(HW_/4);
    const float* base = g_otT + (size_t)c*M_ + p4*4;
    float4 s = make_float4(0,0,0,0);
    #pragma unroll 8
    for (int b = 0; b < B_; b++){
        float4 v = *(const float4*)(base + (size_t)b*HW_);
        s.x += v.x; s.y += v.y; s.z += v.z; s.w += v.w;
    }
    const float inv = 1.0f/B_;
    float4 m = make_float4(s.x*inv, s.y*inv, s.z*inv, s.w*inv);
    ((float4*)g_otmeanT)[i4] = m;
    int p = p4*4;
    float4 f = make_float4(fe[(size_t)(p+0)*C_ + c], fe[(size_t)(p+1)*C_ + c],
                           fe[(size_t)(p+2)*C_ + c], fe[(size_t)(p+3)*C_ + c]);
    ((float4*)g_femixT)[i4] = make_float4(m.x+f.x, m.y+f.y, m.z+f.z, m.w+f.w);
}

// ----- xmeanT[c2][p]: c2<C from mean_b(xc); c2>=C copy otmeanT --------------
__global__ void xmean_k(){
    int i4 = blockIdx.x*blockDim.x + threadIdx.x;
    if (i4 >= HW_*C2_/4) return;
    int c2 = i4 / (HW_/4), p4 = i4 - c2*(HW_/4);
    if (c2 < C_){
        const float* base = g_xc + (size_t)c2*M_ + p4*4;
        float4 s = make_float4(0,0,0,0);
        #pragma unroll 8
        for (int b = 0; b < B_; b++){
            float4 v = *(const float4*)(base + (size_t)b*HW_);
            s.x += v.x; s.y += v.y; s.z += v.z; s.w += v.w;
        }
        const float inv = 1.0f/B_;
        ((float4*)g_xmeanT)[i4] = make_float4(s.x*inv, s.y*inv, s.z*inv, s.w*inv);
    } else {
        ((float4*)g_xmeanT)[i4] = ((const float4*)g_otmeanT)[(size_t)(c2-C_)*(HW_/4) + p4];
    }
}

// ---------------- SIMT NN GEMM on channel-major small tensors --------------
template<int EPI>
__global__ __launch_bounds__(256) void cmgemm_k(
        const float* __restrict__ W, const float* __restrict__ X,
        const float* __restrict__ bias, float* __restrict__ Cout,
        int M, int N, int K)
{
    __shared__ float As[16][68];
    __shared__ float Bs[16][68];
    int t = threadIdx.x;
    int m0 = blockIdx.y*64, n0 = blockIdx.x*64;
    int ty = t >> 4, tx = t & 15;
    float acc[4][4];
    #pragma unroll
    for (int i = 0; i < 4; i++){ acc[i][0]=0;acc[i][1]=0;acc[i][2]=0;acc[i][3]=0; }

    int am = t >> 2, akk = (t & 3)*4;
    int bk = t >> 4, bf = (t & 15)*4;

    for (int k0 = 0; k0 < K; k0 += 16){
        float4 wa = *(const float4*)&W[(size_t)(m0+am)*K + k0 + akk];
        float4 xb = *(const float4*)&X[(size_t)(k0+bk)*N + n0 + bf];
        __syncthreads();
        As[akk+0][am] = wa.x; As[akk+1][am] = wa.y;
        As[akk+2][am] = wa.z; As[akk+3][am] = wa.w;
        *(float4*)&Bs[bk][bf] = xb;
        __syncthreads();
        #pragma unroll
        for (int k = 0; k < 16; k++){
            float a[4], b[4];
            #pragma unroll
            for (int i = 0; i < 4; i++) a[i] = As[k][ty*4+i];
            #pragma unroll
            for (int j = 0; j < 4; j++) b[j] = Bs[k][tx*4+j];
            #pragma unroll
            for (int i = 0; i < 4; i++)
                #pragma unroll
                for (int j = 0; j < 4; j++) acc[i][j] += a[i]*b[j];
        }
    }
    #pragma unroll
    for (int i = 0; i < 4; i++){
        int m = m0 + ty*4 + i;
        float bm = bias[m];
        float4 v;
        float* vp = &v.x;
        #pragma unroll
        for (int j = 0; j < 4; j++){
            float u = acc[i][j] + bm;
            if (EPI == 1){
                u = fmaxf(u, 0.f);
                u = expf(-u * g_dval[n0 + tx*4 + j]);
            }
            vp[j] = u;
        }
        *(float4*)&Cout[(size_t)m*N + n0 + tx*4] = v;
    }
}

// ------------------------ tf32 tensor-core NN GEMM -------------------------
// 512 threads, 16 warps (4x4), BM=128, BN=192, BK=16, warp tile 32x48.
// EPI 0: cm store. EPI 1: NCHW scatter. EPI 3: LN over 192 cols * silu(Z)
// (requires gridDim.x == 1).
__device__ __forceinline__ float to_tf32(float x){
    uint32_t u; asm("cvt.rna.tf32.f32 %0, %1;" : "=r"(u) : "f"(x));
    return __uint_as_float(u);
}
__device__ __forceinline__ void mma_tf32(float c[4], const uint32_t a[4], const uint32_t b[2]){
    asm volatile("mma.sync.aligned.m16n8k8.row.col.f32.tf32.tf32.f32 "
        "{%0,%1,%2,%3}, {%4,%5,%6,%7}, {%8,%9}, {%0,%1,%2,%3};"
        : "+f"(c[0]), "+f"(c[1]), "+f"(c[2]), "+f"(c[3])
        : "r"(a[0]), "r"(a[1]), "r"(a[2]), "r"(a[3]), "r"(b[0]), "r"(b[1]));
}

template<int EPI>
__global__ __launch_bounds__(512) void tgemm_k(
        const float* __restrict__ X, const float* __restrict__ Wm,
        const float* __restrict__ bias, float* __restrict__ Cout,
        int K,
        const float* __restrict__ gam = nullptr,
        const float* __restrict__ bet = nullptr,
        const float* __restrict__ Z = nullptr)
{
    __shared__ float As[2][16][136];
    __shared__ float Bs[2][16][200];
    __shared__ float redS[4][128], redQ[4][128];
    const int t = threadIdx.x;
    const int lane = t & 31, warp = t >> 5;       // 0..15
    const int gid = lane >> 2, tig = lane & 3;
    const int wm = warp & 3, wn = warp >> 2;      // 4 x 4
    const int m0 = wm*32, n0 = wn*48;
    const int row0 = blockIdx.y*128, col0 = blockIdx.x*192;

    float acc[2][6][4];
    #pragma unroll
    for (int mt = 0; mt < 2; mt++)
        #pragma unroll
        for (int nt = 0; nt < 6; nt++)
            #pragma unroll
            for (int q = 0; q < 4; q++) acc[mt][nt][q] = 0.f;

    // A: one float4 per thread (16 k-rows x 32 f4-cols)
    const int af4 = t & 31, ak = t >> 5;
    const float* Ag = X + (size_t)ak*M_ + row0 + af4*4;
    // B: 768 float4 total; thread t does idx=t, threads <256 also idx=512+t
    const int brow0 = t >> 2, bk0 = (t & 3)*4;
    const float* Bg0 = Wm + (size_t)(col0 + brow0)*K + bk0;
    const bool has2 = (t < 256);
    const int brow1 = 128 + (t >> 2), bk1 = (t & 3)*4;
    const float* Bg1 = Wm + (size_t)(col0 + brow1)*K + bk1;

    float4 pa, pb0, pb1;
    pa  = *(const float4*)(Ag);
    pb0 = *(const float4*)(Bg0);
    if (has2) pb1 = *(const float4*)(Bg1);

    auto stash = [&](int s){
        *(float4*)&As[s][ak][af4*4] = make_float4(
            to_tf32(pa.x), to_tf32(pa.y), to_tf32(pa.z), to_tf32(pa.w));
        Bs[s][bk0+0][brow0] = to_tf32(pb0.x);
        Bs[s][bk0+1][brow0] = to_tf32(pb0.y);
        Bs[s][bk0+2][brow0] = to_tf32(pb0.z);
        Bs[s][bk0+3][brow0] = to_tf32(pb0.w);
        if (has2){
            Bs[s][bk1+0][brow1] = to_tf32(pb1.x);
            Bs[s][bk1+1][brow1] = to_tf32(pb1.y);
            Bs[s][bk1+2][brow1] = to_tf32(pb1.z);
            Bs[s][bk1+3][brow1] = to_tf32(pb1.w);
        }
    };

    stash(0);
    __syncthreads();

    const int nIter = K >> 4;
    int s = 0;
    for (int it = 0; it < nIter; it++){
        if (it + 1 < nIter){
            int k0 = (it+1) << 4;
            pa  = *(const float4*)(Ag + (size_t)k0*M_);
            pb0 = *(const float4*)(Bg0 + k0);
            if (has2) pb1 = *(const float4*)(Bg1 + k0);
        }
        #pragma unroll
        for (int ks = 0; ks < 16; ks += 8){
            uint32_t af[2][4];
            #pragma unroll
            for (int mt = 0; mt < 2; mt++){
                int mm = m0 + mt*16 + gid;
                af[mt][0] = __float_as_uint(As[s][ks+tig  ][mm]);
                af[mt][1] = __float_as_uint(As[s][ks+tig  ][mm+8]);
                af[mt][2] = __float_as_uint(As[s][ks+tig+4][mm]);
                af[mt][3] = __float_as_uint(As[s][ks+tig+4][mm+8]);
            }
            uint32_t bf[6][2];
            #pragma unroll
            for (int nt = 0; nt < 6; nt++){
                int nn = n0 + nt*8 + gid;
                bf[nt][0] = __float_as_uint(Bs[s][ks+tig  ][nn]);
                bf[nt][1] = __float_as_uint(Bs[s][ks+tig+4][nn]);
            }
            #pragma unroll
            for (int mt = 0; mt < 2; mt++)
                #pragma unroll
                for (int nt = 0; nt < 6; nt++)
                    mma_tf32(acc[mt][nt], af[mt], bf[nt]);
        }
        if (it + 1 < nIter){
            int sn = s ^ 1;
            stash(sn);
            __syncthreads();
            s = sn;
        }
    }

    if (EPI == 3){
        // bias, LayerNorm across all 192 cols of each row, *silu(Z)
        #pragma unroll
        for (int mt = 0; mt < 2; mt++)
            #pragma unroll
            for (int nt = 0; nt < 6; nt++){
                int cc = col0 + n0 + nt*8 + tig*2;
                float b0v = bias[cc], b1v = bias[cc+1];
                acc[mt][nt][0] += b0v; acc[mt][nt][1] += b1v;
                acc[mt][nt][2] += b0v; acc[mt][nt][3] += b1v;
            }
        float sA[2], qA[2], sB[2], qB[2];
        #pragma unroll
        for (int mt = 0; mt < 2; mt++){
            sA[mt]=0.f; qA[mt]=0.f; sB[mt]=0.f; qB[mt]=0.f;
            #pragma unroll
            for (int nt = 0; nt < 6; nt++){
                float v0=acc[mt][nt][0], v1=acc[mt][nt][1];
                float v2=acc[mt][nt][2], v3=acc[mt][nt][3];
                sA[mt]+=v0+v1; qA[mt]+=v0*v0+v1*v1;
                sB[mt]+=v2+v3; qB[mt]+=v2*v2+v3*v3;
            }
            #pragma unroll
            for (int o = 1; o <= 2; o <<= 1){
                sA[mt]+=__shfl_xor_sync(0xffffffffu,sA[mt],o);
                qA[mt]+=__shfl_xor_sync(0xffffffffu,qA[mt],o);
                sB[mt]+=__shfl_xor_sync(0xffffffffu,sB[mt],o);
                qB[mt]+=__shfl_xor_sync(0xffffffffu,qB[mt],o);
            }
        }
        __syncthreads();
        if (tig == 0){
            #pragma unroll
            for (int mt = 0; mt < 2; mt++){
                int rl = m0 + mt*16 + gid;
                redS[wn][rl]   = sA[mt]; redQ[wn][rl]   = qA[mt];
                redS[wn][rl+8] = sB[mt]; redQ[wn][rl+8] = qB[mt];
            }
        }
        __syncthreads();
        const float invC = 1.0f/C_;
        #pragma unroll
        for (int mt = 0; mt < 2; mt++){
            int rl0 = m0 + mt*16 + gid, rl1 = rl0 + 8;
            int r0 = row0 + rl0, r1 = row0 + rl1;
            float s0 = redS[0][rl0]+redS[1][rl0]+redS[2][rl0]+redS[3][rl0];
            float s1 = redS[0][rl1]+redS[1][rl1]+redS[2][rl1]+redS[3][rl1];
            float q0 = redQ[0][rl0]+redQ[1][rl0]+redQ[2][rl0]+redQ[3][rl0];
            float q1 = redQ[0][rl1]+redQ[1][rl1]+redQ[2][rl1]+redQ[3][rl1];
            float mu0 = s0*invC, mu1 = s1*invC;
            float va0 = fmaxf(q0*invC - mu0*mu0, 0.f);
            float va1 = fmaxf(q1*invC - mu1*mu1, 0.f);
            float rs0 = rsqrtf(va0 + 1e-5f), rs1 = rsqrtf(va1 + 1e-5f);
            #pragma unroll
            for (int nt = 0; nt < 6; nt++){
                int cc = col0 + n0 + nt*8 + tig*2;
                float g0 = gam[cc], g1 = gam[cc+1];
                float e0 = bet[cc], e1 = bet[cc+1];
                float z00 = Z[(size_t)cc*M_ + r0], z01 = Z[(size_t)(cc+1)*M_ + r0];
                float z10 = Z[(size_t)cc*M_ + r1], z11 = Z[(size_t)(cc+1)*M_ + r1];
                float o00 = ((acc[mt][nt][0]-mu0)*rs0*g0 + e0) * (z00/(1.f+expf(-z00)));
                float o01 = ((acc[mt][nt][1]-mu0)*rs0*g1 + e1) * (z01/(1.f+expf(-z01)));
                float o10 = ((acc[mt][nt][2]-mu1)*rs1*g0 + e0) * (z10/(1.f+expf(-z10)));
                float o11 = ((acc[mt][nt][3]-mu1)*rs1*g1 + e1) * (z11/(1.f+expf(-z11)));
                Cout[(size_t)cc    *M_ + r0] = o00;
                Cout[(size_t)(cc+1)*M_ + r0] = o01;
                Cout[(size_t)cc    *M_ + r1] = o10;
                Cout[(size_t)(cc+1)*M_ + r1] = o11;
            }
        }
        return;
    }

    #pragma unroll
    for (int mt = 0; mt < 2; mt++){
        #pragma unroll
        for (int nt = 0; nt < 6; nt++){
            int r0 = row0 + m0 + mt*16 + gid;
            int cc = col0 + n0 + nt*8 + tig*2;
            float b0v = bias[cc], b1v = bias[cc+1];
            float v00 = acc[mt][nt][0] + b0v, v01 = acc[mt][nt][1] + b1v;
            float v10 = acc[mt][nt][2] + b0v, v11 = acc[mt][nt][3] + b1v;
            if (EPI == 0){
                Cout[(size_t)cc    *M_ + r0    ] = v00;
                Cout[(size_t)(cc+1)*M_ + r0    ] = v01;
                Cout[(size_t)cc    *M_ + r0 + 8] = v10;
                Cout[(size_t)(cc+1)*M_ + r0 + 8] = v11;
            } else {   // EPI 1: NCHW scatter
                int b0i = r0 / HW_,     p0i = r0 - b0i*HW_;
                int b1i = (r0+8) / HW_, p1i = (r0+8) - b1i*HW_;
                Cout[((size_t)(b0i*C_ + cc  ))*HW_ + p0i] = v00;
                Cout[((size_t)(b0i*C_ + cc+1))*HW_ + p0i] = v01;
                Cout[((size_t)(b1i*C_ + cc  ))*HW_ + p1i] = v10;
                Cout[((size_t)(b1i*C_ + cc+1))*HW_ + p1i] = v11;
            }
        }
    }
}

// ---------------- fused DCT2D * mult * IDCT2D per 56x56 plane --------------
// Folded transforms (mirror symmetry): every matmul has K=28.
// 2 warps per plane (even/odd output rows), 2 planes per block (128 threads).
template<int MODE>
__global__ __launch_bounds__(128) void dct_k(const float* __restrict__ inA,
                                             const float* __restrict__ inB,
                                             float* __restrict__ outA,
                                             const float* __restrict__ multT,
                                             const float* __restrict__ cosB)
{
    extern __shared__ float sh[];
    float* CsH = sh;                     // [56][28] stride 29
    float* CbF = sh + 56*29;             // [28][56] stride 58
    const int tid  = threadIdx.x;
    const int wid  = tid >> 5, lane = tid & 31;
    const int pl   = wid >> 1;
    const int p    = wid & 1;
    float* P0 = sh + 56*29 + 28*58 + pl*(2*56*PST);
    float* P1 = P0 + 56*PST;

    for (int idx = tid; idx < 56*28; idx += 128){
        int n = idx/28, k = idx - n*28;
        CsH[n*29 + k] = g_cos[n*56 + k];
    }
    for (int idx = tid; idx < 28*56; idx += 128){
        int k = idx/56, m = idx - k*56;
        CbF[k*58 + m] = cosB[k*56 + m];
    }

    const int id = blockIdx.x*2 + pl;
    int b, s = 0, c;
    if (MODE == 0){ b = id / C_; c = id - b*C_; }
    else { b = id / C2_; int rr = id - b*C2_; s = rr / C_; c = rr - s*C_; }
    const float* pinA = inA + (size_t)c*M_ + (size_t)b*HW_;
    const float* pinB = (MODE==1) ? inB + (size_t)c*M_ + (size_t)b*HW_ : nullptr;

    {
        int tl = tid & 63;
        for (int f = tl; f < 1568; f += 64){
            int r = f/28, q = f - r*28;
            if (MODE == 0){
                *(ull*)&P0[r*PST + 2*q] = *(const ull*)(pinA + r*56 + 2*q);
            } else {
                int par = q/14, u = (q - par*14)*2;
                const float* src = par ? pinB : pinA;
                *(ull*)&P0[r*PST + par*28 + u] = *(const ull*)(src + r*56 + 28*s + u);
            }
        }
    }
    __syncthreads();

    const bool act = (lane < 28);
    const int ri = lane >> 2;
    const int tc = (lane & 3)*14;
    const int coff = (MODE==1 && tc >= 28) ? 28 : 0;
    ull acc[4][7];
    ull bvec[7];

    auto rowfold = [&](){
        for (int idx = lane; idx < 1568; idx += 32){
            int hh = idx/56, w = idx - hh*56;
            float a = P0[hh*PST + w], bb = P0[(55-hh)*PST + w];
            P1[(28*p + hh)*PST + w] = p ? (a - bb) : (a + bb);
        }
    };
    auto colfold = [&](){
        for (int idx = lane; idx < 784; idx += 32){
            int nn = idx/28, wt = idx - nn*28;
            int n = 2*nn + p;
            float a = P0[n*PST + wt], bb = P0[n*PST + 55 - wt];
            if (MODE == 0){
                P1[(28*p + nn)*PST + 2*wt]     = a + bb;
                P1[(28*p + nn)*PST + 2*wt + 1] = a - bb;
            } else {
                P1[(28*p + nn)*PST + wt]      = a + bb;
                P1[(28*p + nn)*PST + 28 + wt] = a - bb;
            }
        }
    };
    auto mmRow = [&](){
        #pragma unroll
        for (int i = 0; i < 4; i++)
            #pragma unroll
            for (int j = 0; j < 7; j++) acc[i][j] = 0ULL;
        #pragma unroll 4
        for (int k = 0; k < 28; k++){
            const float* brow = &P1[(28*p + k)*PST + tc];
            #pragma unroll
            for (int j = 0; j < 7; j++) bvec[j] = *(const ull*)(brow + 2*j);
            #pragma unroll
            for (int i = 0; i < 4; i++){
                int n = 2*(ri*4 + i) + p;
                ull ad = dup2(CsH[n*29 + k]);
                #pragma unroll
                for (int j = 0; j < 7; j++) fma2(acc[i][j], ad, bvec[j]);
            }
        }
    };
    auto mmCol = [&](){
        #pragma unroll
        for (int i = 0; i < 4; i++)
            #pragma unroll
            for (int j = 0; j < 7; j++) acc[i][j] = 0ULL;
        #pragma unroll 4
        for (int k = 0; k < 28; k++){
            const float* brow = &CbF[k*58 + tc];
            #pragma unroll
            for (int j = 0; j < 7; j++) bvec[j] = *(const ull*)(brow + 2*j);
            #pragma unroll
            for (int i = 0; i < 4; i++){
                int sr = 28*p + ri*4 + i;
                ull ad;
                if (MODE == 0) ad = *(const ull*)&P1[sr*PST + 2*k];
                else           ad = dup2(P1[sr*PST + k + coff]);
                #pragma unroll
                for (int j = 0; j < 7; j++) fma2(acc[i][j], ad, bvec[j]);
            }
        }
    };

    rowfold();
    __syncthreads();
    if (act){
        mmRow();
        #pragma unroll
        for (int i = 0; i < 4; i++){
            int n = 2*(ri*4 + i) + p;
            #pragma unroll
            for (int j = 0; j < 7; j++) *(ull*)&P0[n*PST + tc + 2*j] = acc[i][j];
        }
    }
    __syncwarp();
    colfold();
    __syncwarp();
    if (act){
        mmCol();
        int par = (MODE==1) ? tc/28 : 0;
        const float* mp = multT + (size_t)(c + C_*par)*HW_;
        int mc = (MODE==1) ? (28*s + (tc - par*28)) : tc;
        #pragma unroll
        for (int i = 0; i < 4; i++){
            int n = 2*(ri*4 + i) + p;
            #pragma unroll
            for (int j = 0; j < 7; j++){
                ull mv = *(const ull*)&mp[n*56 + mc + 2*j];
                *(ull*)&P0[n*PST + tc + 2*j] = mul2(acc[i][j], mv);
            }
        }
    }
    __syncthreads();
    rowfold();
    __syncthreads();
    if (act){
        mmRow();
        #pragma unroll
        for (int i = 0; i < 4; i++){
            int n = 2*(ri*4 + i) + p;
            #pragma unroll
            for (int j = 0; j < 7; j++) *(ull*)&P0[n*PST + tc + 2*j] = acc[i][j];
        }
    }
    __syncwarp();
    colfold();
    __syncwarp();
    if (act){
        mmCol();
        int par = (MODE==1) ? tc/28 : 0;
        float* op = outA + (size_t)(c + C_*par)*M_ + (size_t)b*HW_;
        int oc = (MODE==1) ? (28*s + (tc - par*28)) : tc;
        #pragma unroll
        for (int i = 0; i < 4; i++){
            int n = 2*(ri*4 + i) + p;
            #pragma unroll
            for (int j = 0; j < 7; j++)
                *(ull*)&op[n*56 + oc + 2*j] = acc[i][j];
        }
    }
}

// --------------------------------- launch ----------------------------------
extern "C" void kernel_launch(void* const* d_in, const int* in_sizes, int n_in,
                              void* d_out, int out_size)
{
    const float* x        = (const float*)d_in[0];
    const float* fe       = (const float*)d_in[1];
    const float* ot       = (const float*)d_in[2];
    const float* dw_w     = (const float*)d_in[3];
    const float* dw_b     = (const float*)d_in[4];
    const float* lin_w    = (const float*)d_in[5];
    const float* lin_b    = (const float*)d_in[6];
    const float* tok_w    = (const float*)d_in[7];
    const float* tok_b    = (const float*)d_in[8];
    const float* lin2_w   = (const float*)d_in[9];
    const float* lin2_b   = (const float*)d_in[10];
    const float* tok2_w   = (const float*)d_in[11];
    const float* tok2_b   = (const float*)d_in[12];
    const float* lin3_w   = (const float*)d_in[13];
    const float* lin3_b   = (const float*)d_in[14];
    const float* norm_g   = (const float*)d_in[15];
    const float* norm_b   = (const float*)d_in[16];
    const float* out_w    = (const float*)d_in[17];
    const float* out_b    = (const float*)d_in[18];
    float* out = (float*)d_out;

    float *y0, *t1, *xc, *otT, *xd, *yg;
    float *femixT, *mult1T, *xmeanT, *skftT, *mult2T;
    float *cosT, *cosP;
    cudaGetSymbolAddress((void**)&y0,     g_y0);
    cudaGetSymbolAddress((void**)&t1,     g_t1);
    cudaGetSymbolAddress((void**)&xc,     g_xc);
    cudaGetSymbolAddress((void**)&otT,    g_otT);
    cudaGetSymbolAddress((void**)&xd,     g_xd);
    cudaGetSymbolAddress((void**)&yg,     g_yg);
    cudaGetSymbolAddress((void**)&femixT, g_femixT);
    cudaGetSymbolAddress((void**)&mult1T, g_mult1T);
    cudaGetSymbolAddress((void**)&xmeanT, g_xmeanT);
    cudaGetSymbolAddress((void**)&skftT,  g_skftT);
    cudaGetSymbolAddress((void**)&mult2T, g_mult2T);
    cudaGetSymbolAddress((void**)&cosT,   g_cosT);
    cudaGetSymbolAddress((void**)&cosP,   g_cosP);

    const int DCT_SMEM = (56*29 + 28*58 + 2*2*56*PST) * 4;   // 64960 B
    cudaFuncSetAttribute(dct_k<0>, cudaFuncAttributeMaxDynamicSharedMemorySize, DCT_SMEM);
    cudaFuncSetAttribute(dct_k<1>, cudaFuncAttributeMaxDynamicSharedMemorySize, DCT_SMEM);

    init_k<<<(HW_+255)/256, 256>>>();
    dwconv_k<<<B_*C_, 256>>>(x, dw_w, dw_b);
    transp_k<<<dim3(C_/32, M_/32), 256>>>(ot);
    otfemix_k<<<(HW_*C_/4 + 255)/256, 256>>>(fe);

    // mult1T = exp(-relu(tok_w @ femixT + b) * dval)
    cmgemm_k<1><<<dim3(HW_/64, C_/64), 256>>>(tok_w, femixT, tok_b, mult1T,
                                              C_, HW_, C_);
    // t1 = lin_w @ y0  (tf32 TC, 512 threads)
    tgemm_k<0><<<dim3(2, M_/128), 512>>>(y0, lin_w, lin_b, t1, C_);
    // xc = dct-filter-idct (mode 0)
    dct_k<0><<<B_*C_/2, 128, DCT_SMEM>>>(t1, nullptr, xc, mult1T, cosT);

    xmean_k<<<(HW_*C2_/4 + 255)/256, 256>>>();
    // skftT = lin2 @ xmeanT + b
    cmgemm_k<0><<<dim3(HW_/64, C2_/64), 256>>>(lin2_w, xmeanT, lin2_b, skftT,
                                               C2_, HW_, C2_);
    // mult2T = exp(-relu(tok2 @ skftT + b) * dval)
    cmgemm_k<1><<<dim3(HW_/64, C2_/64), 256>>>(tok2_w, skftT, tok2_b, mult2T,
                                               C2_, HW_, C2_);
    // xd = interleaved dct-filter-idct (mode 1)
    dct_k<1><<<B_*C2_/2, 128, DCT_SMEM>>>(xc, otT, xd, mult2T, cosP);

    // yg = LN(lin3 @ xd + b) * silu(z)   [fused epilogue, grid.x == 1]
    tgemm_k<3><<<dim3(1, M_/128), 512>>>(xd, lin3_w, lin3_b, yg, C2_,
                                         norm_g, norm_b, t1 + (size_t)C_*M_);
    // out = out_w @ yg, NCHW
    tgemm_k<1><<<dim3(1, M_/128), 512>>>(yg, out_w, out_b, out, C_);
}